// round 1
// baseline (speedup 1.0000x reference)
#include <cuda_runtime.h>
#include <math.h>

#define BB    8
#define N1    2048
#define N2    8192
#define C1    256
#define C2    128
#define CIN   384
#define MOUT  256
#define NTOT  (BB*N2)   // 65536 columns total

// ---------------- scratch (static __device__ arrays; no allocation) ----------
__device__ int    g_idx[BB*N2*3];
__device__ float  g_wgt[BB*N2*3];
__device__ float  g_interp[(size_t)BB*C1*N2];   // 67 MB  interpolated feat1
__device__ float  g_Y1[(size_t)BB*MOUT*N2];     // 67 MB  layer-1 raw output
__device__ float  g_scale1[MOUT], g_shift1[MOUT];
__device__ float  g_scale2[MOUT], g_shift2[MOUT];

// ---------------- 1) three_nn: top-3 nearest sparse points ------------------
__global__ void knn_kernel(const float* __restrict__ xyz2,
                           const float* __restrict__ xyz1)
{
    __shared__ float sx[N1], sy[N1], sz[N1];
    const int b = blockIdx.y;
    const float* p1 = xyz1 + (size_t)b * 3 * N1;
    for (int t = threadIdx.x; t < N1; t += blockDim.x) {
        sx[t] = p1[t];
        sy[t] = p1[N1 + t];
        sz[t] = p1[2*N1 + t];
    }
    __syncthreads();

    const int n = blockIdx.x * blockDim.x + threadIdx.x;
    const float* p2 = xyz2 + (size_t)b * 3 * N2;
    const float px = p2[n], py = p2[N2 + n], pz = p2[2*N2 + n];

    float d0 = 3.4e38f, d1 = 3.4e38f, d2v = 3.4e38f;
    int   i0 = 0, i1 = 0, i2 = 0;
    #pragma unroll 4
    for (int j = 0; j < N1; ++j) {
        float dx = px - sx[j];
        float dy = py - sy[j];
        float dz = pz - sz[j];
        float d = dx*dx + dy*dy + dz*dz;
        if (d < d2v) {
            if (d < d1) {
                d2v = d1; i2 = i1;
                if (d < d0) { d1 = d0; i1 = i0; d0 = d; i0 = j; }
                else        { d1 = d;  i1 = j; }
            } else { d2v = d; i2 = j; }
        }
    }
    d0  = fmaxf(d0,  1e-10f);
    d1  = fmaxf(d1,  1e-10f);
    d2v = fmaxf(d2v, 1e-10f);
    float r0 = 1.0f / d0, r1 = 1.0f / d1, r2 = 1.0f / d2v;
    float inv = 1.0f / (r0 + r1 + r2);
    size_t base = ((size_t)b * N2 + n) * 3;
    g_idx[base]   = i0; g_idx[base+1] = i1; g_idx[base+2] = i2;
    g_wgt[base]   = r0*inv; g_wgt[base+1] = r1*inv; g_wgt[base+2] = r2*inv;
}

// ---------------- 2) weighted gather of feat1 -> g_interp -------------------
__global__ void interp_kernel(const float* __restrict__ feat1)
{
    const int b = blockIdx.y;
    const int n = blockIdx.x * blockDim.x + threadIdx.x;
    size_t base = ((size_t)b * N2 + n) * 3;
    const int   i0 = g_idx[base], i1 = g_idx[base+1], i2 = g_idx[base+2];
    const float w0 = g_wgt[base], w1 = g_wgt[base+1], w2 = g_wgt[base+2];
    const float* f1 = feat1 + (size_t)b * C1 * N1;
    float* X = g_interp + (size_t)b * C1 * N2 + n;
    #pragma unroll 4
    for (int c = 0; c < C1; ++c) {
        const float* row = f1 + c * N1;
        X[(size_t)c * N2] = w0 * row[i0] + w1 * row[i1] + w2 * row[i2];
    }
}

// ---------------- 3/5) tiled fp32 GEMM, optional concat input / fused BN ----
// out[b, m, n2] = sum_k Wm[m,k] * A[k, (b,n2)] + bias[m]
// CONCAT: rows [0,C1) come from A1 (g_interp), rows [C1,K) from A2 (feat2)
// FUSE:   A element -> relu(a*scale[k] + shift[k])   (layer-1 BN+ReLU)
template<int K, bool CONCAT, bool FUSE>
__global__ void __launch_bounds__(256)
gemm_kernel(const float* __restrict__ Wm, const float* __restrict__ bias,
            const float* __restrict__ A1, const float* __restrict__ A2,
            const float* __restrict__ scale, const float* __restrict__ shift,
            float* __restrict__ out)
{
    constexpr int BM = 64, BN = 128, BK = 16;
    __shared__ float Ws[BK][BM];    // W transposed tile
    __shared__ float Xs[BK][BN];

    const int tid = threadIdx.x;
    const int tx  = tid & 15;       // n sub-tile (8 cols each)
    const int ty  = tid >> 4;       // m sub-tile (4 rows each)

    const int nglob = blockIdx.x * BN;
    const int b     = nglob >> 13;          // /8192
    const int n2    = nglob & (N2 - 1);
    const int m0    = blockIdx.y * BM;

    const float* A1b = A1 + (size_t)b * (CONCAT ? C1 : K) * N2 + n2;
    const float* A2b = CONCAT ? (A2 + (size_t)b * C2 * N2 + n2) : nullptr;

    float acc[4][8];
    #pragma unroll
    for (int r = 0; r < 4; ++r)
        #pragma unroll
        for (int c = 0; c < 8; ++c) acc[r][c] = 0.0f;

    const int wm = tid >> 2;            // 0..63 : m within tile
    const int wk = (tid & 3) * 4;       // 0,4,8,12 : k within tile

    for (int k0 = 0; k0 < K; k0 += BK) {
        // --- load W tile (64x16), store transposed ---
        float4 wv = *(const float4*)(Wm + (size_t)(m0 + wm) * K + k0 + wk);
        Ws[wk+0][wm] = wv.x; Ws[wk+1][wm] = wv.y;
        Ws[wk+2][wm] = wv.z; Ws[wk+3][wm] = wv.w;

        // --- load A tile (16x128) ---
        #pragma unroll
        for (int e = 0; e < 2; ++e) {
            const int ent = tid + e * 256;
            const int k   = ent >> 5;           // 0..15
            const int nq  = (ent & 31) * 4;     // col 0..124
            const int kg  = k0 + k;
            const float* src;
            if (CONCAT)
                src = (kg < C1) ? (A1b + (size_t)kg * N2)
                                : (A2b + (size_t)(kg - C1) * N2);
            else
                src = A1b + (size_t)kg * N2;
            float4 v = *(const float4*)(src + nq);
            if (FUSE) {
                const float sc = scale[kg], sh = shift[kg];
                v.x = fmaxf(fmaf(v.x, sc, sh), 0.0f);
                v.y = fmaxf(fmaf(v.y, sc, sh), 0.0f);
                v.z = fmaxf(fmaf(v.z, sc, sh), 0.0f);
                v.w = fmaxf(fmaf(v.w, sc, sh), 0.0f);
            }
            *(float4*)&Xs[k][nq] = v;
        }
        __syncthreads();

        #pragma unroll
        for (int kk = 0; kk < BK; ++kk) {
            const float4 a  = *(const float4*)&Ws[kk][ty * 4];
            const float4 x0 = *(const float4*)&Xs[kk][tx * 8];
            const float4 x1 = *(const float4*)&Xs[kk][tx * 8 + 4];
            const float av[4] = {a.x, a.y, a.z, a.w};
            const float xv[8] = {x0.x, x0.y, x0.z, x0.w, x1.x, x1.y, x1.z, x1.w};
            #pragma unroll
            for (int r = 0; r < 4; ++r)
                #pragma unroll
                for (int c = 0; c < 8; ++c)
                    acc[r][c] = fmaf(av[r], xv[c], acc[r][c]);
        }
        __syncthreads();
    }

    float* ob = out + (size_t)b * MOUT * N2 + n2;
    #pragma unroll
    for (int r = 0; r < 4; ++r) {
        const int m = m0 + ty * 4 + r;
        const float bv = bias[m];
        float4 o0 = {acc[r][0] + bv, acc[r][1] + bv, acc[r][2] + bv, acc[r][3] + bv};
        float4 o1 = {acc[r][4] + bv, acc[r][5] + bv, acc[r][6] + bv, acc[r][7] + bv};
        *(float4*)(ob + (size_t)m * N2 + tx * 8)     = o0;
        *(float4*)(ob + (size_t)m * N2 + tx * 8 + 4) = o1;
    }
}

// ---------------- 4/6) BN training-mode stats -> per-channel affine ---------
__global__ void stats_kernel(const float* __restrict__ Y,
                             const float* __restrict__ gamma,
                             const float* __restrict__ beta,
                             float* __restrict__ scale,
                             float* __restrict__ shift)
{
    const int c = blockIdx.x;
    double s = 0.0, ss = 0.0;
    for (int t = threadIdx.x; t < NTOT; t += blockDim.x) {
        const int b = t >> 13;
        const int n = t & (N2 - 1);
        const float v = Y[(size_t)b * MOUT * N2 + (size_t)c * N2 + n];
        s  += (double)v;
        ss += (double)v * (double)v;
    }
    __shared__ double rs[256], rss[256];
    rs[threadIdx.x] = s; rss[threadIdx.x] = ss;
    __syncthreads();
    for (int o = 128; o > 0; o >>= 1) {
        if (threadIdx.x < o) {
            rs[threadIdx.x]  += rs[threadIdx.x + o];
            rss[threadIdx.x] += rss[threadIdx.x + o];
        }
        __syncthreads();
    }
    if (threadIdx.x == 0) {
        const double mean = rs[0] / (double)NTOT;
        const double var  = rss[0] / (double)NTOT - mean * mean;
        const float istd  = (float)(1.0 / sqrt(var + 1e-3));
        const float sc    = gamma[c] * istd;
        scale[c] = sc;
        shift[c] = beta[c] - (float)mean * sc;
    }
}

// ---------------- 7) in-place BN+ReLU of layer-2 output ---------------------
__global__ void finalize_kernel(float* __restrict__ out)
{
    const size_t i4 = (size_t)blockIdx.x * blockDim.x + threadIdx.x; // float4 idx
    const int c = (int)((i4 >> 11) & 255);   // 8192/4 = 2048 float4 per row
    float4* p = (float4*)out + i4;
    float4 v = *p;
    const float sc = g_scale2[c], sh = g_shift2[c];
    v.x = fmaxf(fmaf(v.x, sc, sh), 0.0f);
    v.y = fmaxf(fmaf(v.y, sc, sh), 0.0f);
    v.z = fmaxf(fmaf(v.z, sc, sh), 0.0f);
    v.w = fmaxf(fmaf(v.w, sc, sh), 0.0f);
    *p = v;
}

// ---------------- launch ----------------------------------------------------
extern "C" void kernel_launch(void* const* d_in, const int* in_sizes, int n_in,
                              void* d_out, int out_size)
{
    const float* xyz2  = (const float*)d_in[0];
    const float* xyz1  = (const float*)d_in[1];
    const float* feat2 = (const float*)d_in[2];
    const float* feat1 = (const float*)d_in[3];
    const float* W1    = (const float*)d_in[4];
    const float* b1    = (const float*)d_in[5];
    const float* g1    = (const float*)d_in[6];
    const float* be1   = (const float*)d_in[7];
    const float* W2    = (const float*)d_in[8];
    const float* b2    = (const float*)d_in[9];
    const float* g2    = (const float*)d_in[10];
    const float* be2   = (const float*)d_in[11];
    float* out = (float*)d_out;

    float *p_interp, *p_Y1, *p_s1, *p_sh1, *p_s2, *p_sh2;
    cudaGetSymbolAddress((void**)&p_interp, g_interp);
    cudaGetSymbolAddress((void**)&p_Y1,     g_Y1);
    cudaGetSymbolAddress((void**)&p_s1,     g_scale1);
    cudaGetSymbolAddress((void**)&p_sh1,    g_shift1);
    cudaGetSymbolAddress((void**)&p_s2,     g_scale2);
    cudaGetSymbolAddress((void**)&p_sh2,    g_shift2);

    knn_kernel<<<dim3(N2/256, BB), 256>>>(xyz2, xyz1);
    interp_kernel<<<dim3(N2/256, BB), 256>>>(feat1);

    // layer 1: y1 = W1 @ [interp; feat2] + b1   (raw, stats afterwards)
    gemm_kernel<CIN, true, false><<<dim3(NTOT/128, MOUT/64), 256>>>(
        W1, b1, p_interp, feat2, nullptr, nullptr, p_Y1);
    stats_kernel<<<MOUT, 256>>>(p_Y1, g1, be1, p_s1, p_sh1);

    // layer 2: y2 = W2 @ relu(bn(y1)) + b2  -> d_out (raw)
    gemm_kernel<MOUT, false, true><<<dim3(NTOT/128, MOUT/64), 256>>>(
        W2, b2, p_Y1, nullptr, p_s1, p_sh1, out);
    stats_kernel<<<MOUT, 256>>>(out, g2, be2, p_s2, p_sh2);

    // in-place bn+relu on d_out
    finalize_kernel<<<(NTOT * MOUT / 4) / 256, 256>>>(out);
}